// round 17
// baseline (speedup 1.0000x reference)
#include <cuda_runtime.h>
#include <cuda_bf16.h>
#include <cstdint>

// Problem constants
#define B_    256
#define T_    2048
#define F_    64
#define H_    512
#define C_    128

// Partitioning: 64 gate-row chunks (32 rows = 8 h-units) x 2 batch chunks (128) = 128 CTAs
// 16 warps: group A (0-7) = m-tile w, K panels 0-4; group B (8-15) = m-tile w-8, K panels 5-8
#define NJ    64
#define NCTA  128
#define NTHR  512
#define JTH   8
#define NROW  32
#define MB    128

// SMEM layout
#define OFF_A     0                        // A bufs: 8 warps x 2 x 4KB = 65536
#define OFF_AB    65536                    // B bufs: 8 warps x 4KB = 32768
#define OFF_WF    98304                    // gate weight frags: 36*4*32*16 = 73728
#define OFF_HN    172032                   // 8 warps x 8jj x 16 f32 = 4096
#define OFF_DS    176128                   // decoder staging: 8 x 512B = 4096
#define OFF_WDF   180224                   // decoder W frags: 16*32*8 = 4096
#define OFF_BSUM  184320                   // 32 f32
#define OFF_BD    184448                   // 128 f32
#define SMEM_BYTES 184960

// ---------------- device globals (static scratch; zero-initialized) ---------
__device__ __nv_bfloat16 g_hhi[2][B_][H_];
__device__ __nv_bfloat16 g_hlo[2][B_][H_];
__device__ float g_part[2][NJ][B_][C_];
__device__ unsigned int g_count = 0;
__device__ volatile unsigned int g_sense = 0;

__device__ __forceinline__ float sigm(float x) { return 1.0f / (1.0f + expf(-x)); }
__device__ __forceinline__ uint32_t sw128(uint32_t off) { return off ^ ((off >> 3) & 0x70); }

__device__ __forceinline__ void pack_hilo(float f0, float f1, uint32_t& hi, uint32_t& lo) {
    __nv_bfloat16 h0 = __float2bfloat16(f0), h1 = __float2bfloat16(f1);
    float r0 = f0 - __bfloat162float(h0), r1 = f1 - __bfloat162float(h1);
    __nv_bfloat16 l0 = __float2bfloat16(r0), l1 = __float2bfloat16(r1);
    hi = (uint32_t)__bfloat16_as_ushort(h0) | ((uint32_t)__bfloat16_as_ushort(h1) << 16);
    lo = (uint32_t)__bfloat16_as_ushort(l0) | ((uint32_t)__bfloat16_as_ushort(l1) << 16);
}

#define LDMX4(r0,r1,r2,r3,addr) \
    asm volatile("ldmatrix.sync.aligned.m8n8.x4.shared.b16 {%0,%1,%2,%3}, [%4];" \
                 : "=r"(r0),"=r"(r1),"=r"(r2),"=r"(r3) : "r"(addr))

#define LDMX2(r0,r1,addr) \
    asm volatile("ldmatrix.sync.aligned.m8n8.x2.shared.b16 {%0,%1}, [%2];" \
                 : "=r"(r0),"=r"(r1) : "r"(addr))

#define MMA16816(d,a0,a1,a2,a3,b0,b1) \
    asm volatile("mma.sync.aligned.m16n8k16.row.col.f32.bf16.bf16.f32 " \
                 "{%0,%1,%2,%3}, {%4,%5,%6,%7}, {%8,%9}, {%0,%1,%2,%3};" \
                 : "+f"(d[0]),"+f"(d[1]),"+f"(d[2]),"+f"(d[3]) \
                 : "r"(a0),"r"(a1),"r"(a2),"r"(a3), "r"(b0),"r"(b1))

__global__ void __launch_bounds__(NTHR, 1) lstm_hmma_kernel(
    const float* __restrict__ X,
    const float* __restrict__ Wih,
    const float* __restrict__ Whh,
    const float* __restrict__ bih,
    const float* __restrict__ bhh,
    const float* __restrict__ Wd,
    const float* __restrict__ bd,
    float* __restrict__ out)
{
    extern __shared__ char smc[];
    const uint32_t smb = (uint32_t)__cvta_generic_to_shared(smc);
    uint4*  wfrag = (uint4*)(smc + OFF_WF);
    uint2*  wdf   = (uint2*)(smc + OFF_WDF);
    float*  bsum  = (float*)(smc + OFF_BSUM);
    float*  bds   = (float*)(smc + OFF_BD);

    const int tid  = threadIdx.x;
    const int cta  = blockIdx.x;
    const int jb   = cta >> 1;
    const int bb   = cta & 1;
    const int J0h  = jb * JTH;
    const int b0   = bb * MB;
    const int wrp  = tid >> 5;
    const int lane = tid & 31;
    const int rloc = lane >> 1;
    const int seg  = lane & 1;
    const bool isA = (wrp < 8);
    const int mw   = isA ? wrp : (wrp - 8);     // m-tile id 0..7

    // ---- one-time init ----
    for (int idx = tid; idx < 36 * 4 * 32; idx += NTHR) {
        int ks = idx >> 7, rem = idx & 127;
        int nt = rem >> 5, l = rem & 31;
        int n = nt * 8 + (l >> 2);
        int jj = n >> 2, g = n & 3;
        int grow = g * H_ + J0h + jj;
        int kA = ks * 16 + (l & 3) * 2;
        float w[4];
        #pragma unroll
        for (int e = 0; e < 4; ++e) {
            int k = kA + (e & 1) + (e >> 1) * 8;
            w[e] = (k < F_) ? Wih[(size_t)grow * F_ + k]
                            : Whh[(size_t)grow * H_ + (k - F_)];
        }
        uint32_t h0, l0, h1, l1;
        pack_hilo(w[0], w[1], h0, l0);
        pack_hilo(w[2], w[3], h1, l1);
        wfrag[idx] = make_uint4(h0, h1, l0, l1);
    }
    for (int idx = tid; idx < 16 * 32; idx += NTHR) {
        int nt = idx >> 5, l = idx & 31;
        int c0 = nt * 8 + (l >> 2);
        int k0 = (l & 3) * 2;
        float w0 = Wd[(size_t)c0 * H_ + J0h + k0];
        float w1 = Wd[(size_t)c0 * H_ + J0h + k0 + 1];
        uint32_t hi, lo;
        pack_hilo(w0, w1, hi, lo);
        wdf[idx] = make_uint2(hi, lo);
    }
    if (tid < NROW) {
        int jj = tid >> 2, g = tid & 3;
        bsum[tid] = bih[g * H_ + J0h + jj] + bhh[g * H_ + J0h + jj];
    }
    if (tid < C_) bds[tid] = bd[tid];
    __syncthreads();

    const int jbit = (lane >> 1) & 1;
    float bi[4], bf[4], bg[4], bo[4];
    #pragma unroll
    for (int nt = 0; nt < 4; ++nt) {
        int jj = 2 * nt + jbit;
        bi[nt] = bsum[jj * 4 + 0]; bf[nt] = bsum[jj * 4 + 1];
        bg[nt] = bsum[jj * 4 + 2]; bo[nt] = bsum[jj * 4 + 3];
    }

    float cst[4] = {0.f, 0.f, 0.f, 0.f};
    const int mloc = (lane >> 2) + ((lane & 1) << 3);
    float* hnw = (float*)(smc + OFF_HN) + mw * 128;
    const uint32_t dsw = smb + OFF_DS + mw * 512;

    const uint32_t awarp = smb + OFF_A + mw * 8192;          // A double-buf
    const uint32_t bwarp = smb + OFF_AB + mw * 4096;         // B single-buf
    float* accex = (float*)(smc + OFF_AB + mw * 4096 + 2048);// B acc exchange (2KB)

    uint32_t swst[4], swld[4];
    #pragma unroll
    for (int j = 0; j < 4; ++j)
        swst[j] = sw128((uint32_t)(rloc * 128 + seg * 64 + j * 16));
    #pragma unroll
    for (int ks = 0; ks < 4; ++ks)
        swld[ks] = sw128((uint32_t)((lane & 15) * 128 + ks * 32 + (lane >> 4) * 16));

    const int myb = b0 + mw * 16 + rloc;
    uint4 hr[8];
    int cur = 0;

    // ---- preloop ----
    if (isA) {
        const uint4* xp = (const uint4*)(X + ((size_t)myb * T_) * F_ + seg * 32);
        uint4 xf[8];
        #pragma unroll
        for (int i = 0; i < 8; ++i) xf[i] = __ldcg(xp + i);
        #pragma unroll
        for (int j = 0; j < 4; ++j) {
            float4 fa = *(float4*)&xf[2 * j], fb = *(float4*)&xf[2 * j + 1];
            uint32_t h0,l0,h1,l1,h2,l2,h3,l3;
            pack_hilo(fa.x, fa.y, h0, l0); pack_hilo(fa.z, fa.w, h1, l1);
            pack_hilo(fb.x, fb.y, h2, l2); pack_hilo(fb.z, fb.w, h3, l3);
            asm volatile("st.shared.v4.b32 [%0], {%1,%2,%3,%4};"
                         :: "r"(awarp + swst[j]), "r"(h0),"r"(h1),"r"(h2),"r"(h3));
            asm volatile("st.shared.v4.b32 [%0], {%1,%2,%3,%4};"
                         :: "r"(awarp + 2048 + swst[j]), "r"(l0),"r"(l1),"r"(l2),"r"(l3));
        }
        #pragma unroll
        for (int j = 0; j < 4; ++j) {
            hr[j]     = __ldcg((const uint4*)&g_hhi[0][myb][seg * 32 + j * 8]);
            hr[4 + j] = __ldcg((const uint4*)&g_hlo[0][myb][seg * 32 + j * 8]);
        }
    } else {
        #pragma unroll
        for (int j = 0; j < 4; ++j) {
            hr[j]     = __ldcg((const uint4*)&g_hhi[0][myb][256 + seg * 32 + j * 8]);
            hr[4 + j] = __ldcg((const uint4*)&g_hlo[0][myb][256 + seg * 32 + j * 8]);
        }
    }
    __syncthreads();

    for (int t = 0; t < T_; ++t) {
        const int par = t & 1;

        float acc[4][4];
        #pragma unroll
        for (int nt = 0; nt < 4; ++nt)
            #pragma unroll
            for (int i = 0; i < 4; ++i) acc[nt][i] = 0.f;

        if (isA) {
            // ---- group A: panels 0..4 (x + h[0:256)) ----
            #pragma unroll 1
            for (int p = 0; p < 5; ++p) {
                const uint32_t bufc = awarp + cur * 4096;
                const uint32_t bufn = awarp + (cur ^ 1) * 4096;
                __syncwarp();
                if (p < 4) {
                    #pragma unroll
                    for (int j = 0; j < 4; ++j) {
                        uint4 h = hr[j], l = hr[4 + j];
                        asm volatile("st.shared.v4.b32 [%0], {%1,%2,%3,%4};"
                                     :: "r"(bufn + swst[j]), "r"(h.x),"r"(h.y),"r"(h.z),"r"(h.w));
                        asm volatile("st.shared.v4.b32 [%0], {%1,%2,%3,%4};"
                                     :: "r"(bufn + 2048 + swst[j]), "r"(l.x),"r"(l.y),"r"(l.z),"r"(l.w));
                    }
                } else if (t + 1 < T_) {
                    #pragma unroll
                    for (int j = 0; j < 4; ++j) {
                        float4 fa = *(float4*)&hr[2 * j], fb = *(float4*)&hr[2 * j + 1];
                        uint32_t h0,l0,h1,l1,h2,l2,h3,l3;
                        pack_hilo(fa.x, fa.y, h0, l0); pack_hilo(fa.z, fa.w, h1, l1);
                        pack_hilo(fb.x, fb.y, h2, l2); pack_hilo(fb.z, fb.w, h3, l3);
                        asm volatile("st.shared.v4.b32 [%0], {%1,%2,%3,%4};"
                                     :: "r"(bufn + swst[j]), "r"(h0),"r"(h1),"r"(h2),"r"(h3));
                        asm volatile("st.shared.v4.b32 [%0], {%1,%2,%3,%4};"
                                     :: "r"(bufn + 2048 + swst[j]), "r"(l0),"r"(l1),"r"(l2),"r"(l3));
                    }
                }
                __syncwarp();
                if (p <= 2) {
                    int kb = (p + 1) * 64 + seg * 32;
                    #pragma unroll
                    for (int j = 0; j < 4; ++j) {
                        hr[j]     = __ldcg((const uint4*)&g_hhi[par][myb][kb + j * 8]);
                        hr[4 + j] = __ldcg((const uint4*)&g_hlo[par][myb][kb + j * 8]);
                    }
                } else if (p == 3 && t + 1 < T_) {
                    const uint4* xp = (const uint4*)(X + ((size_t)myb * T_ + (t + 1)) * F_ + seg * 32);
                    #pragma unroll
                    for (int i = 0; i < 8; ++i) hr[i] = __ldcg(xp + i);
                }
                #pragma unroll
                for (int ks = 0; ks < 4; ++ks) {
                    uint32_t ah0, ah1, ah2, ah3, al0, al1, al2, al3;
                    LDMX4(ah0, ah1, ah2, ah3, bufc + swld[ks]);
                    LDMX4(al0, al1, al2, al3, bufc + 2048 + swld[ks]);
                    const uint4* wf = &wfrag[((p * 4 + ks) * 4) * 32 + lane];
                    #pragma unroll
                    for (int nt = 0; nt < 4; ++nt) {
                        uint4 b = wf[nt * 32];
                        MMA16816(acc[nt], ah0, ah1, ah2, ah3, b.x, b.y);
                        MMA16816(acc[nt], al0, al1, al2, al3, b.x, b.y);
                        MMA16816(acc[nt], ah0, ah1, ah2, ah3, b.z, b.w);
                    }
                }
                cur ^= 1;
            }
        } else {
            // ---- group B: panels 5..8 (h[256:512)), single buffer ----
            #pragma unroll 1
            for (int p = 5; p < 9; ++p) {
                __syncwarp();
                #pragma unroll
                for (int j = 0; j < 4; ++j) {
                    uint4 h = hr[j], l = hr[4 + j];
                    asm volatile("st.shared.v4.b32 [%0], {%1,%2,%3,%4};"
                                 :: "r"(bwarp + swst[j]), "r"(h.x),"r"(h.y),"r"(h.z),"r"(h.w));
                    asm volatile("st.shared.v4.b32 [%0], {%1,%2,%3,%4};"
                                 :: "r"(bwarp + 2048 + swst[j]), "r"(l.x),"r"(l.y),"r"(l.z),"r"(l.w));
                }
                __syncwarp();
                if (p < 8) {
                    int kb = p * 64 + seg * 32;
                    #pragma unroll
                    for (int j = 0; j < 4; ++j) {
                        hr[j]     = __ldcg((const uint4*)&g_hhi[par][myb][kb + j * 8]);
                        hr[4 + j] = __ldcg((const uint4*)&g_hlo[par][myb][kb + j * 8]);
                    }
                }
                #pragma unroll
                for (int ks = 0; ks < 4; ++ks) {
                    uint32_t ah0, ah1, ah2, ah3, al0, al1, al2, al3;
                    LDMX4(ah0, ah1, ah2, ah3, bwarp + swld[ks]);
                    LDMX4(al0, al1, al2, al3, bwarp + 2048 + swld[ks]);
                    const uint4* wf = &wfrag[((p * 4 + ks) * 4) * 32 + lane];
                    #pragma unroll
                    for (int nt = 0; nt < 4; ++nt) {
                        uint4 b = wf[nt * 32];
                        MMA16816(acc[nt], ah0, ah1, ah2, ah3, b.x, b.y);
                        MMA16816(acc[nt], al0, al1, al2, al3, b.x, b.y);
                        MMA16816(acc[nt], ah0, ah1, ah2, ah3, b.z, b.w);
                    }
                }
            }
            // publish B partial accumulators
            __syncwarp();
            float4* ex = (float4*)((char*)accex + lane * 64);
            #pragma unroll
            for (int nt = 0; nt < 4; ++nt)
                ex[nt] = make_float4(acc[nt][0], acc[nt][1], acc[nt][2], acc[nt][3]);
        }
        __syncthreads();   // B acc visible to A

        if (isA) {
            // ---- reduce + cell update ----
            {
                const float4* ex = (const float4*)((char*)accex + lane * 64);
                #pragma unroll
                for (int nt = 0; nt < 4; ++nt) {
                    float4 v = ex[nt];
                    acc[nt][0] += v.x; acc[nt][1] += v.y;
                    acc[nt][2] += v.z; acc[nt][3] += v.w;
                }
            }
            const int odd = lane & 1;
            #pragma unroll
            for (int nt = 0; nt < 4; ++nt) {
                float t0 = __shfl_xor_sync(0xffffffffu, acc[nt][0], 1);
                float t1 = __shfl_xor_sync(0xffffffffu, acc[nt][1], 1);
                float t2 = __shfl_xor_sync(0xffffffffu, acc[nt][2], 1);
                float t3 = __shfl_xor_sync(0xffffffffu, acc[nt][3], 1);
                float pi = odd ? t2 : acc[nt][0];
                float pf = odd ? t3 : acc[nt][1];
                float pg = odd ? acc[nt][2] : t0;
                float po = odd ? acc[nt][3] : t1;
                pi += bi[nt]; pf += bf[nt]; pg += bg[nt]; po += bo[nt];
                float iv = sigm(pi), fv = sigm(pf), gv = tanhf(pg), ov = sigm(po);
                float cn = fv * cst[nt] + iv * gv;
                cst[nt] = cn;
                hnw[(2 * nt + jbit) * 16 + mloc] = ov * tanhf(cn);
            }
            __syncwarp();

            // lanes 0-15: decoder staging; lanes 16-31: h writeback
            if (lane < 16) {
                int r = lane;
                float f[8];
                #pragma unroll
                for (int kk = 0; kk < 8; ++kk) f[kk] = fmaxf(hnw[kk * 16 + r], 0.f);
                uint32_t dh[4], dl[4];
                #pragma unroll
                for (int j = 0; j < 4; ++j) pack_hilo(f[2 * j], f[2 * j + 1], dh[j], dl[j]);
                asm volatile("st.shared.v4.b32 [%0], {%1,%2,%3,%4};"
                             :: "r"(dsw + r * 16), "r"(dh[0]),"r"(dh[1]),"r"(dh[2]),"r"(dh[3]));
                asm volatile("st.shared.v4.b32 [%0], {%1,%2,%3,%4};"
                             :: "r"(dsw + 256 + r * 16), "r"(dl[0]),"r"(dl[1]),"r"(dl[2]),"r"(dl[3]));
            } else {
                int r = lane - 16;
                float f[8];
                #pragma unroll
                for (int kk = 0; kk < 8; ++kk) f[kk] = hnw[kk * 16 + r];
                uint32_t ph[4], pl[4];
                #pragma unroll
                for (int j = 0; j < 4; ++j) pack_hilo(f[2 * j], f[2 * j + 1], ph[j], pl[j]);
                int b = b0 + mw * 16 + r;
                *(uint4*)&g_hhi[par ^ 1][b][J0h] = make_uint4(ph[0], ph[1], ph[2], ph[3]);
                *(uint4*)&g_hlo[par ^ 1][b][J0h] = make_uint4(pl[0], pl[1], pl[2], pl[3]);
            }
            __syncwarp();

            // decoder GEMM via HMMA
            {
                uint32_t a0h, a1h, a0l, a1l;
                LDMX2(a0h, a1h, dsw + (lane & 15) * 16);
                LDMX2(a0l, a1l, dsw + 256 + (lane & 15) * 16);
                const int prow = b0 + mw * 16 + (lane >> 2);
                const int pcol = (lane & 3) * 2;
                #pragma unroll
                for (int nt = 0; nt < 16; ++nt) {
                    uint2 wv = wdf[nt * 32 + lane];
                    float d[4] = {0.f, 0.f, 0.f, 0.f};
                    MMA16816(d, a0h, a1h, 0u, 0u, wv.x, 0u);
                    MMA16816(d, a0l, a1l, 0u, 0u, wv.x, 0u);
                    MMA16816(d, a0h, a1h, 0u, 0u, wv.y, 0u);
                    *(float2*)&g_part[par][jb][prow][nt * 8 + pcol]     = make_float2(d[0], d[1]);
                    *(float2*)&g_part[par][jb][prow + 8][nt * 8 + pcol] = make_float2(d[2], d[3]);
                }
            }
        }

        // ---- grid-wide sync ----
        {
            unsigned target = (unsigned)((t & 1) ^ 1);
            __syncthreads();
            if (tid == 0) {
                __threadfence();
                unsigned v = atomicAdd(&g_count, 1u);
                if (v == NCTA - 1) {
                    g_count = 0;
                    __threadfence();
                    g_sense = target;
                } else {
                    while (g_sense != target) { __nanosleep(64); }
                }
                __threadfence();
            }
            __syncthreads();
        }

        // ---- prefetch next step's first panels ----
        if (t + 1 < T_) {
            int kb = (isA ? 0 : 256) + seg * 32;
            #pragma unroll
            for (int j = 0; j < 4; ++j) {
                hr[j]     = __ldcg((const uint4*)&g_hhi[par ^ 1][myb][kb + j * 8]);
                hr[4 + j] = __ldcg((const uint4*)&g_hlo[par ^ 1][myb][kb + j * 8]);
            }
        }

        // ---- phase 4 on warps 8-9 (group B, lighter loaded) ----
        if (wrp == 8 || wrp == 9) {
            const int b = cta * 2 + (wrp - 8);
            float v[4];
            #pragma unroll
            for (int j = 0; j < 4; ++j) v[j] = bds[lane + 32 * j];
            #pragma unroll 8
            for (int j2 = 0; j2 < NJ; ++j2) {
                const float* pp = &g_part[par][j2][b][0];
                #pragma unroll
                for (int j = 0; j < 4; ++j) v[j] += __ldcg(pp + lane + 32 * j);
            }
            float m = fmaxf(fmaxf(v[0], v[1]), fmaxf(v[2], v[3]));
            #pragma unroll
            for (int o = 16; o; o >>= 1)
                m = fmaxf(m, __shfl_xor_sync(0xffffffffu, m, o));
            float e[4], s = 0.f;
            #pragma unroll
            for (int j = 0; j < 4; ++j) { e[j] = expf(v[j] - m); s += e[j]; }
            #pragma unroll
            for (int o = 16; o; o >>= 1)
                s += __shfl_xor_sync(0xffffffffu, s, o);
            float inv = 1.0f / s;
            #pragma unroll
            for (int j = 0; j < 4; ++j)
                out[(size_t)b * (T_ * C_) + (size_t)t * C_ + lane + 32 * j] = e[j] * inv;
        }
    }

    // ---- restore parity-0 h to zeros (replay determinism) ----
    if (tid < MB) {
        *(uint4*)&g_hhi[0][b0 + tid][J0h] = make_uint4(0, 0, 0, 0);
    } else if (tid < 2 * MB) {
        *(uint4*)&g_hlo[0][b0 + (tid - MB)][J0h] = make_uint4(0, 0, 0, 0);
    }
}

extern "C" void kernel_launch(void* const* d_in, const int* in_sizes, int n_in,
                              void* d_out, int out_size) {
    (void)in_sizes; (void)n_in; (void)out_size;
    const float* x   = (const float*)d_in[0];
    const float* Wih = (const float*)d_in[1];
    const float* Whh = (const float*)d_in[2];
    const float* bih = (const float*)d_in[3];
    const float* bhh = (const float*)d_in[4];
    const float* Wd  = (const float*)d_in[5];
    const float* bd  = (const float*)d_in[6];
    float* out = (float*)d_out;

    cudaFuncSetAttribute(lstm_hmma_kernel,
                         cudaFuncAttributeMaxDynamicSharedMemorySize, SMEM_BYTES);
    lstm_hmma_kernel<<<NCTA, NTHR, SMEM_BYTES>>>(x, Wih, Whh, bih, bhh, Wd, bd, out);
}